// round 1
// baseline (speedup 1.0000x reference)
#include <cuda_runtime.h>
#include <cstddef>

// Problem constants
#define BB 512   // batch
#define TT 512   // timesteps
#define FF 64    // input features
#define H1 128   // layer1 hidden
#define G1 512   // 4*H1
#define H2 64    // layer2 hidden
#define G2 256   // 4*H2

// ---------------------------------------------------------------------------
// Device scratch (static allocations are allowed; cudaMalloc is not)
// ---------------------------------------------------------------------------
__device__ float g_Wp1[FF * G1];        // W1 permuted: [f][j*4+gate]
__device__ float g_bp1[G1];
__device__ float g_Up1[H1 * G1];        // U1 permuted: [k][j*4+gate]
__device__ float g_Wp2[H1 * G2];
__device__ float g_bp2[G2];
__device__ float g_Up2[H2 * G2];
__device__ float g_xw1[(size_t)TT * BB * G1];  // [t][b][j*4+gate]  512 MB
__device__ float g_h1[(size_t)TT * BB * H1];   // [t][b][j]         128 MB
__device__ float g_xw2[(size_t)TT * BB * G2];  // [t][b][j*4+gate]  256 MB
__device__ float g_h2[BB * H2];                // final layer2 h

__device__ __forceinline__ float sigf(float x) {
    return __fdividef(1.0f, 1.0f + __expf(-x));
}

#define FMA16(h4, u4)                                                        \
    do {                                                                     \
        z[0][0] += h4.x * u4.x; z[0][1] += h4.x * u4.y;                      \
        z[0][2] += h4.x * u4.z; z[0][3] += h4.x * u4.w;                      \
        z[1][0] += h4.y * u4.x; z[1][1] += h4.y * u4.y;                      \
        z[1][2] += h4.y * u4.z; z[1][3] += h4.y * u4.w;                      \
        z[2][0] += h4.z * u4.x; z[2][1] += h4.z * u4.y;                      \
        z[2][2] += h4.z * u4.z; z[2][3] += h4.z * u4.w;                      \
        z[3][0] += h4.w * u4.x; z[3][1] += h4.w * u4.y;                      \
        z[3][2] += h4.w * u4.z; z[3][3] += h4.w * u4.w;                      \
    } while (0)

// ---------------------------------------------------------------------------
// Prep: permute weights so column n = j*4 + gate  (gate order i,f,g,o)
// src column for layer1: gate*128 + j ; layer2: gate*64 + j
// ---------------------------------------------------------------------------
__global__ void prep_kernel(const float* __restrict__ W1, const float* __restrict__ U1,
                            const float* __restrict__ b1, const float* __restrict__ W2,
                            const float* __restrict__ U2, const float* __restrict__ b2)
{
    int i = blockIdx.x * blockDim.x + threadIdx.x;
    if (i < FF * G1) {
        int f = i >> 9, n = i & 511;
        int j = n >> 2, gi = n & 3;
        g_Wp1[i] = W1[f * G1 + gi * H1 + j];
    }
    if (i < G1) {
        int j = i >> 2, gi = i & 3;
        g_bp1[i] = b1[gi * H1 + j];
    }
    if (i < H1 * G1) {
        int k = i >> 9, n = i & 511;
        int j = n >> 2, gi = n & 3;
        g_Up1[i] = U1[k * G1 + gi * H1 + j];
    }
    if (i < H1 * G2) {
        int k = i >> 8, n = i & 255;
        int j = n >> 2, gi = n & 3;
        g_Wp2[i] = W2[k * G2 + gi * H2 + j];
    }
    if (i < G2) {
        int j = i >> 2, gi = i & 3;
        g_bp2[i] = b2[gi * H2 + j];
    }
    if (i < H2 * G2) {
        int k = i >> 8, n = i & 255;
        int j = n >> 2, gi = n & 3;
        g_Up2[i] = U2[k * G2 + gi * H2 + j];
    }
}

// ---------------------------------------------------------------------------
// Tiled GEMM:  C[m][n] = sum_k A_row(m)[k] * W[k][n] + bias[n]
// m = t*512 + b ; A row address = t*sT + b*sB (handles the [B,T,F] gather of x)
// CTA tile: 128 (m) x 64 (n), K chunked by 64 (fully smem-resident per chunk)
// ---------------------------------------------------------------------------
#define AS_LD 132
#define GEMM_SMEM ((64 * AS_LD + 64 * 64) * 4)

__global__ __launch_bounds__(256) void gemm_kernel(
    const float* __restrict__ A, const float* __restrict__ W,
    const float* __restrict__ bias, float* __restrict__ C,
    int sT, int sB, int K, int N)
{
    extern __shared__ float sm[];
    float* As = sm;               // [64][AS_LD]  k-major (transposed)
    float* Ws = sm + 64 * AS_LD;  // [64][64]
    const int tid = threadIdx.x;
    const int tx = tid & 15, ty = tid >> 4;
    const int mt = blockIdx.x * 128;
    const int nt = blockIdx.y * 64;

    float acc[8][4];
#pragma unroll
    for (int q = 0; q < 8; q++)
#pragma unroll
        for (int c = 0; c < 4; c++) acc[q][c] = 0.f;

    for (int kt = 0; kt < K; kt += 64) {
        // A tile: 128 rows x 64 k, transposed into smem
#pragma unroll
        for (int i = 0; i < 8; i++) {
            int li = tid + i * 256;
            int m  = li >> 4;
            int c4 = (li & 15) << 2;
            int gm = mt + m;
            int t  = gm >> 9;
            int b  = gm & 511;
            float4 v = *(const float4*)(A + (size_t)t * sT + (size_t)b * sB + kt + c4);
            As[(c4 + 0) * AS_LD + m] = v.x;
            As[(c4 + 1) * AS_LD + m] = v.y;
            As[(c4 + 2) * AS_LD + m] = v.z;
            As[(c4 + 3) * AS_LD + m] = v.w;
        }
        // W tile: 64 k x 64 n
#pragma unroll
        for (int i = 0; i < 4; i++) {
            int li = tid + i * 256;
            int k  = li >> 4;
            int c4 = (li & 15) << 2;
            *(float4*)(Ws + k * 64 + c4) = *(const float4*)(W + (size_t)(kt + k) * N + nt + c4);
        }
        __syncthreads();
#pragma unroll 8
        for (int k = 0; k < 64; k++) {
            float4 a0 = *(const float4*)(As + k * AS_LD + (ty << 2));
            float4 a1 = *(const float4*)(As + k * AS_LD + 64 + (ty << 2));
            float4 w  = *(const float4*)(Ws + k * 64 + (tx << 2));
            acc[0][0] += a0.x * w.x; acc[0][1] += a0.x * w.y; acc[0][2] += a0.x * w.z; acc[0][3] += a0.x * w.w;
            acc[1][0] += a0.y * w.x; acc[1][1] += a0.y * w.y; acc[1][2] += a0.y * w.z; acc[1][3] += a0.y * w.w;
            acc[2][0] += a0.z * w.x; acc[2][1] += a0.z * w.y; acc[2][2] += a0.z * w.z; acc[2][3] += a0.z * w.w;
            acc[3][0] += a0.w * w.x; acc[3][1] += a0.w * w.y; acc[3][2] += a0.w * w.z; acc[3][3] += a0.w * w.w;
            acc[4][0] += a1.x * w.x; acc[4][1] += a1.x * w.y; acc[4][2] += a1.x * w.z; acc[4][3] += a1.x * w.w;
            acc[5][0] += a1.y * w.x; acc[5][1] += a1.y * w.y; acc[5][2] += a1.y * w.z; acc[5][3] += a1.y * w.w;
            acc[6][0] += a1.z * w.x; acc[6][1] += a1.z * w.y; acc[6][2] += a1.z * w.z; acc[6][3] += a1.z * w.w;
            acc[7][0] += a1.w * w.x; acc[7][1] += a1.w * w.y; acc[7][2] += a1.w * w.z; acc[7][3] += a1.w * w.w;
        }
        __syncthreads();
    }
    float4 bv = *(const float4*)(bias + nt + (tx << 2));
#pragma unroll
    for (int q = 0; q < 8; q++) {
        int m = mt + ((q < 4) ? ((ty << 2) + q) : (64 + (ty << 2) + q - 4));
        float4 o;
        o.x = acc[q][0] + bv.x;
        o.y = acc[q][1] + bv.y;
        o.z = acc[q][2] + bv.z;
        o.w = acc[q][3] + bv.w;
        *(float4*)(C + (size_t)m * N + nt + (tx << 2)) = o;
    }
}

// ---------------------------------------------------------------------------
// Layer-1 recurrence. 128 CTAs x 256 threads; CTA owns 4 batch rows.
// thread = (j in [0,128), ks in {0,1}); ks splits the K=128 reduction.
// U1: 104 rows in smem (ks0: rows 0..51, ks1: rows 64..115), 24 rows in regs
// (ks0: 52..63, ks1: 116..127). Per k: LDS.128 U(4 gates) + bcast LDS.128 h(4 b)
// + 16 FMA. Gates fused per hidden unit j; c lives in ks=0 registers.
// ---------------------------------------------------------------------------
#define REC1_SMEM ((104 * 512 + 2 * 128 * 4 + 128 * 16) * 4)  // 225280 B

__global__ __launch_bounds__(256) void rec1_kernel()
{
    extern __shared__ float sm[];
    float* Us = sm;                 // [104][512]
    float* hs = sm + 104 * 512;     // [2][128][4] double-buffered h (b-major float4)
    float* ex = hs + 1024;          // [128][16] ks=1 partials

    const int tid  = threadIdx.x;
    const int j    = tid & 127;
    const int ks   = tid >> 7;
    const int brow = blockIdx.x << 2;

    // cooperative load of the smem-resident U rows (with row remap)
    for (int i = tid; i < 104 * 128; i += 256) {
        int s = i >> 7;
        int c = (i & 127) << 2;
        int krow = (s < 52) ? s : (s + 12);
        *(float4*)(Us + s * 512 + c) = *(const float4*)(g_Up1 + krow * 512 + c);
    }
    // register-resident U rows
    const int rbase = ks ? 116 : 52;
    float4 uw[12];
#pragma unroll
    for (int r = 0; r < 12; r++)
        uw[r] = *(const float4*)(g_Up1 + (rbase + r) * 512 + (j << 2));
    for (int i = tid; i < 512; i += 256) hs[i] = 0.f;  // h0 = 0 (buffer 0)
    float cc[4] = {0.f, 0.f, 0.f, 0.f};
    __syncthreads();

    const float* up0 = Us + (ks * 52) * 512 + (j << 2);
    int buf = 0;
    for (int t = 0; t < TT; t++) {
        float z[4][4];
#pragma unroll
        for (int b = 0; b < 4; b++)
#pragma unroll
            for (int g = 0; g < 4; g++) z[b][g] = 0.f;

        float4 xv[4];
        if (ks == 0) {  // issue early; consumed only after the long FMA loop
#pragma unroll
            for (int b = 0; b < 4; b++)
                xv[b] = *(const float4*)(g_xw1 + ((size_t)(t * BB + brow + b) << 9) + (j << 2));
        }

        const float* hb = hs + buf * 512;
        const float* hp = hb + (ks ? 256 : 0);
        {
            const float* up = up0;
#pragma unroll 4
            for (int r = 0; r < 52; r++) {
                float4 h4 = *(const float4*)(hp + (r << 2));
                float4 u4 = *(const float4*)(up);
                up += 512;
                FMA16(h4, u4);
            }
        }
        {
            const float* hp2 = hb + (rbase << 2);
#pragma unroll
            for (int r = 0; r < 12; r++) {
                float4 h4 = *(const float4*)(hp2 + (r << 2));
                float4 u4 = uw[r];
                FMA16(h4, u4);
            }
        }
        if (ks) {
#pragma unroll
            for (int b = 0; b < 4; b++)
                *(float4*)(ex + (j << 4) + (b << 2)) =
                    make_float4(z[b][0], z[b][1], z[b][2], z[b][3]);
        } else {
#pragma unroll
            for (int b = 0; b < 4; b++) {
                z[b][0] += xv[b].x; z[b][1] += xv[b].y;
                z[b][2] += xv[b].z; z[b][3] += xv[b].w;
            }
        }
        __syncthreads();
        if (ks == 0) {
            float* hn = hs + (buf ^ 1) * 512;
            float hv[4];
#pragma unroll
            for (int b = 0; b < 4; b++) {
                float4 e = *(const float4*)(ex + (j << 4) + (b << 2));
                float zi = z[b][0] + e.x;
                float zf = z[b][1] + e.y;
                float zg = z[b][2] + e.z;
                float zo = z[b][3] + e.w;
                float ig = sigf(zi);
                float fg = sigf(zf);
                float gg = fmaxf(zg, 0.f);
                float og = sigf(zo);
                cc[b] = fg * cc[b] + ig * gg;
                hv[b] = og * fmaxf(cc[b], 0.f);
                g_h1[((size_t)(t * BB + brow + b) << 7) + j] = hv[b];
            }
            *(float4*)(hn + (j << 2)) = make_float4(hv[0], hv[1], hv[2], hv[3]);
        }
        __syncthreads();
        buf ^= 1;
    }
}

// ---------------------------------------------------------------------------
// Layer-2 recurrence. 128 CTAs x 128 threads; (j in [0,64), ks in {0,1}).
// U2 (64 KB) fully smem-resident. Only final h written out.
// ---------------------------------------------------------------------------
#define REC2_SMEM ((64 * 256 + 2 * 64 * 4 + 64 * 16) * 4)  // 71680 B

__global__ __launch_bounds__(128) void rec2_kernel()
{
    extern __shared__ float sm[];
    float* Us = sm;                // [64][256]
    float* hs = sm + 64 * 256;     // [2][64][4]
    float* ex = hs + 512;          // [64][16]

    const int tid  = threadIdx.x;
    const int j    = tid & 63;
    const int ks   = tid >> 6;
    const int brow = blockIdx.x << 2;

    for (int i = tid; i < 64 * 64; i += 128) {
        int s = i >> 6;
        int c = (i & 63) << 2;
        *(float4*)(Us + s * 256 + c) = *(const float4*)(g_Up2 + s * 256 + c);
    }
    for (int i = tid; i < 256; i += 128) hs[i] = 0.f;
    float cc[4] = {0.f, 0.f, 0.f, 0.f};
    __syncthreads();

    const float* up0 = Us + (ks * 32) * 256 + (j << 2);
    int buf = 0;
    for (int t = 0; t < TT; t++) {
        float z[4][4];
#pragma unroll
        for (int b = 0; b < 4; b++)
#pragma unroll
            for (int g = 0; g < 4; g++) z[b][g] = 0.f;

        float4 xv[4];
        if (ks == 0) {
#pragma unroll
            for (int b = 0; b < 4; b++)
                xv[b] = *(const float4*)(g_xw2 + ((size_t)(t * BB + brow + b) << 8) + (j << 2));
        }
        const float* hb = hs + buf * 256;
        const float* hp = hb + (ks ? 128 : 0);
        const float* up = up0;
#pragma unroll 4
        for (int r = 0; r < 32; r++) {
            float4 h4 = *(const float4*)(hp + (r << 2));
            float4 u4 = *(const float4*)(up);
            up += 256;
            FMA16(h4, u4);
        }
        if (ks) {
#pragma unroll
            for (int b = 0; b < 4; b++)
                *(float4*)(ex + (j << 4) + (b << 2)) =
                    make_float4(z[b][0], z[b][1], z[b][2], z[b][3]);
        } else {
#pragma unroll
            for (int b = 0; b < 4; b++) {
                z[b][0] += xv[b].x; z[b][1] += xv[b].y;
                z[b][2] += xv[b].z; z[b][3] += xv[b].w;
            }
        }
        __syncthreads();
        if (ks == 0) {
            float* hn = hs + (buf ^ 1) * 256;
            float hv[4];
#pragma unroll
            for (int b = 0; b < 4; b++) {
                float4 e = *(const float4*)(ex + (j << 4) + (b << 2));
                float zi = z[b][0] + e.x;
                float zf = z[b][1] + e.y;
                float zg = z[b][2] + e.z;
                float zo = z[b][3] + e.w;
                float ig = sigf(zi);
                float fg = sigf(zf);
                float gg = fmaxf(zg, 0.f);
                float og = sigf(zo);
                cc[b] = fg * cc[b] + ig * gg;
                hv[b] = og * fmaxf(cc[b], 0.f);
                if (t == TT - 1)
                    g_h2[((brow + b) << 6) + j] = hv[b];
            }
            *(float4*)(hn + (j << 2)) = make_float4(hv[0], hv[1], hv[2], hv[3]);
        }
        __syncthreads();
        buf ^= 1;
    }
}

// ---------------------------------------------------------------------------
// Dense head: out[b] = (h2[b] @ Wd1 + bd1) @ Wd2 + bd2
// ---------------------------------------------------------------------------
__global__ void dense_kernel(const float* __restrict__ Wd1, const float* __restrict__ bd1,
                             const float* __restrict__ Wd2, const float* __restrict__ bd2,
                             float* __restrict__ out)
{
    int b = blockIdx.x * blockDim.x + threadIdx.x;
    if (b >= BB) return;
    float h[H2];
#pragma unroll
    for (int k = 0; k < H2; k++) h[k] = g_h2[(b << 6) + k];
    float acc = bd2[0];
    for (int d = 0; d < 25; d++) {
        float s = bd1[d];
#pragma unroll
        for (int k = 0; k < H2; k++) s += h[k] * Wd1[k * 25 + d];
        acc += s * Wd2[d];
    }
    out[b] = acc;
}

// ---------------------------------------------------------------------------
// Launch
// ---------------------------------------------------------------------------
extern "C" void kernel_launch(void* const* d_in, const int* in_sizes, int n_in,
                              void* d_out, int out_size)
{
    const float* x   = (const float*)d_in[0];
    const float* W1  = (const float*)d_in[1];
    const float* U1  = (const float*)d_in[2];
    const float* b1  = (const float*)d_in[3];
    const float* W2  = (const float*)d_in[4];
    const float* U2  = (const float*)d_in[5];
    const float* b2  = (const float*)d_in[6];
    const float* Wd1 = (const float*)d_in[7];
    const float* bd1 = (const float*)d_in[8];
    const float* Wd2 = (const float*)d_in[9];
    const float* bd2 = (const float*)d_in[10];
    float* out = (float*)d_out;

    cudaFuncSetAttribute(gemm_kernel, cudaFuncAttributeMaxDynamicSharedMemorySize, GEMM_SMEM);
    cudaFuncSetAttribute(rec1_kernel, cudaFuncAttributeMaxDynamicSharedMemorySize, REC1_SMEM);
    cudaFuncSetAttribute(rec2_kernel, cudaFuncAttributeMaxDynamicSharedMemorySize, REC2_SMEM);

    float *pWp1, *pbp1, *pWp2, *pbp2, *pxw1, *pxw2, *ph1;
    cudaGetSymbolAddress((void**)&pWp1, g_Wp1);
    cudaGetSymbolAddress((void**)&pbp1, g_bp1);
    cudaGetSymbolAddress((void**)&pWp2, g_Wp2);
    cudaGetSymbolAddress((void**)&pbp2, g_bp2);
    cudaGetSymbolAddress((void**)&pxw1, g_xw1);
    cudaGetSymbolAddress((void**)&pxw2, g_xw2);
    cudaGetSymbolAddress((void**)&ph1,  g_h1);

    // 1. permute weights into gate-interleaved layout
    prep_kernel<<<256, 256>>>(W1, U1, b1, W2, U2, b2);

    // 2. xW1: x[b][t][:] @ Wp1 -> g_xw1[t][b][:]   (sT=F, sB=T*F gather of x)
    gemm_kernel<<<dim3((TT * BB) / 128, G1 / 64), 256, GEMM_SMEM>>>(
        x, pWp1, pbp1, pxw1, FF, TT * FF, FF, G1);

    // 3. layer-1 recurrence -> g_h1[t][b][:]
    rec1_kernel<<<BB / 4, 256, REC1_SMEM>>>();

    // 4. xW2: h1[t][b][:] @ Wp2 -> g_xw2[t][b][:]  (row-major: sT=B*H1, sB=H1)
    gemm_kernel<<<dim3((TT * BB) / 128, G2 / 64), 256, GEMM_SMEM>>>(
        ph1, pWp2, pbp2, pxw2, BB * H1, H1, H1, G2);

    // 5. layer-2 recurrence -> g_h2[b][:]
    rec2_kernel<<<BB / 4, 128, REC2_SMEM>>>();

    // 6. dense head
    dense_kernel<<<2, 256>>>(Wd1, bd1, Wd2, bd2, out);
}